// round 7
// baseline (speedup 1.0000x reference)
#include <cuda_runtime.h>
#include <cstdint>

#define NB   1024
#define CD   512
#define NN   32
#define TD   2048
#define NT   (NN*TD)      // 65536 rows
#define MT   128          // rows per CTA
#define NTILE (NT/MT)     // 512 CTAs
#define NTHR 512
#define PASSES 8
#define PN   128          // codes per pass
#define CHT  32           // total k-chunks (8 passes x 4)
#define MARGIN 8.0f
#define CMAX 8
#define QS   21.1666666f  // 127/6
#define LAM2 (36.0f/16129.0f)

typedef unsigned long long ull;

// codebook packed in s8 B-fragment layout: [n8(128)][kseg(16)][lane(32)][8B]
__device__ __align__(16) uint8_t g_cb8[(NB/8)*16*32*8];
__device__ float g_cbnorm[NB];
__device__ int   g_counts[NB];
__device__ float g_partials[NTILE];

// smem map (bytes)
#define SA    0        // A s8 frag 64KB  (cand overlay 48KB after GEMM)
#define SB    65536    // B double buffer 2x16KB (qt overlay in output stage)
#define SCBN  98304    // 4KB
#define SIDX  102400   // 512B
#define SWRED 102912   // 64B
#define SMTOT 103040

static __device__ __forceinline__ uint32_t smem_u32(const void* p){
    uint32_t a; asm("{ .reg .u64 t; cvta.to.shared.u64 t, %1; cvt.u32.u64 %0, t; }" : "=r"(a) : "l"(p));
    return a;
}
static __device__ __forceinline__ int q8(float v){
    return __float2int_rn(fminf(fmaxf(v*QS, -127.f), 127.f));
}
static __device__ __forceinline__ void mma_s8(int* c, const uint32_t* a, const uint32_t* bf){
    asm volatile("mma.sync.aligned.m16n8k32.row.col.s32.s8.s8.s32 "
        "{%0,%1,%2,%3}, {%4,%5,%6,%7}, {%8,%9}, {%0,%1,%2,%3};"
        : "+r"(c[0]), "+r"(c[1]), "+r"(c[2]), "+r"(c[3])
        : "r"(a[0]), "r"(a[1]), "r"(a[2]), "r"(a[3]), "r"(bf[0]), "r"(bf[1]));
}

// ---------------- kernel 0: norms + s8 fragment pack + zero counts ----------------
__global__ void k_prep(const float* __restrict__ cb){
    int j = blockIdx.x;
    float s = 0.f;
    for (int c = threadIdx.x; c < CD; c += 128){
        float v = cb[(size_t)j*CD + c];
        s = fmaf(v, v, s);
        int kseg = c >> 5, rem = c & 31;
        int half = rem >> 4, q = (rem >> 2) & 3, byi = rem & 3;
        // B frag: lane = (j&7)*4 + q ; b0 = k 0-15, b1 = k 16-31
        size_t addr = (((size_t)(j >> 3)*16 + kseg)*32 + (j & 7)*4 + q)*8 + half*4 + byi;
        g_cb8[addr] = (uint8_t)(q8(v) & 0xFF);
    }
    #pragma unroll
    for (int o = 16; o; o >>= 1) s += __shfl_xor_sync(~0u, s, o);
    __shared__ float ws[4];
    if ((threadIdx.x & 31) == 0) ws[threadIdx.x >> 5] = s;
    __syncthreads();
    if (threadIdx.x == 0){
        g_cbnorm[j] = (ws[0] + ws[1]) + (ws[2] + ws[3]);
        g_counts[j] = 0;
    }
}

// ---------------- B chunk stage (pure copy of prepacked fragments) ----------------
static __device__ __forceinline__ void issueB(int q, int tid, uint32_t sbase){
    int p = q >> 2, kc = q & 3;
    uint32_t bufb = sbase + SB + (uint32_t)(q & 1)*16384u;
    #pragma unroll
    for (int it = 0; it < 2; ++it){
        int idx = tid + it*NTHR;              // 0..1023 16B units
        int n8l = idx >> 6, rem = idx & 63;
        int ksl = rem >> 4, u = rem & 15;
        const void* src = g_cb8 + (((size_t)(p*16 + n8l)*16 + kc*4 + ksl)*256 + u*16);
        uint32_t dst = bufb + (uint32_t)(n8l*1024 + ksl*256 + u*16);
        asm volatile("cp.async.cg.shared.global [%0], [%1], 16;" :: "r"(dst), "l"(src));
    }
    asm volatile("cp.async.commit_group;");
}

// ---------------- kernel 1: fused s8 GEMM + top3 + exact refine + output ----------------
__global__ __launch_bounds__(NTHR, 1)
void k_main(const float* __restrict__ x, const float* __restrict__ cb, float* __restrict__ out){
    extern __shared__ char sm[];
    const uint32_t sbase = smem_u32(sm);
    const int tid = threadIdx.x, l = tid & 31, wid = tid >> 5;
    const int wm = wid >> 3, wn = wid & 7;    // 2 M-warps x 8 N-warps
    const int b = blockIdx.x, n = b >> 4, t0 = (b & 15) * MT;
    const float* xblk = x + (size_t)n*CD*TD + t0;
    float* outblk     = out + (size_t)n*CD*TD + t0;
    float* cbn_s = (float*)(sm + SCBN);
    int*   sidx  = (int*)(sm + SIDX);
    float* wred  = (float*)(sm + SWRED);
    uint8_t* A8  = (uint8_t*)(sm + SA);

    for (int i = tid; i < NB; i += NTHR) cbn_s[i] = g_cbnorm[i];

    // ---- stage A: x tile -> s8 fragment layout [mt][kseg][lane][16B] ----
    #pragma unroll 2
    for (int it = 0; it < 32; ++it){
        int idx = tid + it*NTHR;              // 0..16383 float4s
        int c = idx >> 5, t4 = (idx & 31)*4;
        float4 v = *(const float4*)(xblk + (size_t)c*TD + t4);
        float vv[4] = {v.x, v.y, v.z, v.w};
        int kseg = c >> 5;
        int lq   = (c >> 2) & 3;
        int kh   = (c >> 4) & 1;
        int byi  = c & 3;
        #pragma unroll
        for (int dt = 0; dt < 4; ++dt){
            int t = t4 + dt;
            int mt = t >> 4;
            int ln = (t & 7)*4 + lq;
            int rg = kh*2 + ((t >> 3) & 1);
            A8[(uint32_t)(((mt*16 + kseg)*32 + ln)*16 + rg*4 + byi)] = (uint8_t)(q8(vv[dt]) & 0xFF);
        }
    }
    __syncthreads();

    issueB(0, tid, sbase);

    uint32_t k3[8][3];
    #pragma unroll
    for (int r = 0; r < 8; ++r){ k3[r][0] = k3[r][1] = k3[r][2] = 0xFFFFFFFFu; }

    for (int p = 0; p < PASSES; ++p){
        int acc[4][2][4];
        #pragma unroll
        for (int ti = 0; ti < 4; ++ti)
            #pragma unroll
            for (int tj = 0; tj < 2; ++tj)
                #pragma unroll
                for (int e = 0; e < 4; ++e) acc[ti][tj][e] = 0;

        for (int kc = 0; kc < 4; ++kc){
            int q = p*4 + kc;
            if (q + 1 < CHT){ issueB(q + 1, tid, sbase); asm volatile("cp.async.wait_group 1;"); }
            else            { asm volatile("cp.async.wait_group 0;"); }
            __syncthreads();
            uint32_t bb = sbase + SB + (uint32_t)(q & 1)*16384u;
            #pragma unroll
            for (int ks = 0; ks < 4; ++ks){
                uint32_t a[4][4], bf[2][2];
                #pragma unroll
                for (int ti = 0; ti < 4; ++ti){
                    uint32_t aaddr = sbase + SA + (uint32_t)((((wm*4 + ti)*16 + kc*4 + ks)*32 + l)*16);
                    asm volatile("ld.shared.v4.b32 {%0,%1,%2,%3}, [%4];"
                        : "=r"(a[ti][0]), "=r"(a[ti][1]), "=r"(a[ti][2]), "=r"(a[ti][3]) : "r"(aaddr));
                }
                #pragma unroll
                for (int tj = 0; tj < 2; ++tj){
                    uint32_t baddr = bb + (uint32_t)((wn*2 + tj)*1024 + ks*256 + l*8);
                    asm volatile("ld.shared.v2.b32 {%0,%1}, [%2];"
                        : "=r"(bf[tj][0]), "=r"(bf[tj][1]) : "r"(baddr));
                }
                #pragma unroll
                for (int ti = 0; ti < 4; ++ti)
                    #pragma unroll
                    for (int tj = 0; tj < 2; ++tj)
                        mma_s8(acc[ti][tj], a[ti], bf[tj]);
            }
            __syncthreads();
        }
        // ---- pass epilogue: approx distances -> per-slot top3 (packed keys) ----
        #pragma unroll
        for (int ti = 0; ti < 4; ++ti)
            #pragma unroll
            for (int tj = 0; tj < 2; ++tj)
                #pragma unroll
                for (int e = 0; e < 4; ++e){
                    int jg = p*PN + wn*16 + tj*8 + (l & 3)*2 + (e & 1);
                    float d = fmaf(-2.f*LAM2, __int2float_rn(acc[ti][tj][e]), cbn_s[jg]) + 32.f;
                    uint32_t key = (__float_as_uint(d) & 0xFFFFFC00u) | (uint32_t)jg;
                    int r = ti*2 + (e >> 1);
                    if (key < k3[r][0]){ k3[r][2]=k3[r][1]; k3[r][1]=k3[r][0]; k3[r][0]=key; }
                    else if (key < k3[r][1]){ k3[r][2]=k3[r][1]; k3[r][1]=key; }
                    else if (key < k3[r][2]){ k3[r][2]=key; }
                }
    }

    // ---- dump candidates (overlay A region): cand[128][96] packed keys ----
    uint32_t* cand = (uint32_t*)(sm + SA);
    __syncthreads();
    #pragma unroll
    for (int r = 0; r < 8; ++r){
        int m = wm*64 + (r >> 1)*16 + (r & 1)*8 + (l >> 2);
        #pragma unroll
        for (int s = 0; s < 3; ++s)
            cand[m*96 + wn*12 + (l & 3)*3 + s] = k3[r][s];
    }
    __syncthreads();

    // ---- per-row pick + exact fp32 refine ----
    if (tid < MT){
        int m = tid;
        uint32_t bk = 0xFFFFFFFFu;
        #pragma unroll 4
        for (int s = 0; s < 96; ++s){
            uint32_t k = cand[m*96 + s];
            if (k < bk) bk = k;
        }
        float dmin = __uint_as_float(bk & 0xFFFFFC00u);
        float thr = dmin + MARGIN;
        int cj[CMAX]; int ncand = 0;
        #pragma unroll 4
        for (int s = 0; s < 96; ++s){
            uint32_t k = cand[m*96 + s];
            float dk = __uint_as_float(k & 0xFFFFFC00u);
            if (dk <= thr && ncand < CMAX) cj[ncand++] = (int)(k & 1023u);
        }
        int jf = (int)(bk & 1023u);
        if (ncand > 1){
            float sacc[CMAX];
            const float* cps[CMAX];
            #pragma unroll
            for (int q2 = 0; q2 < CMAX; ++q2){
                sacc[q2] = 0.f;
                cps[q2] = cb + (size_t)cj[q2 < ncand ? q2 : 0]*CD;
            }
            const float* xr = xblk + m;
            #pragma unroll 4
            for (int c = 0; c < CD; ++c){
                float xv = xr[(size_t)c*TD];
                #pragma unroll
                for (int q2 = 0; q2 < CMAX; ++q2)
                    if (q2 < ncand) sacc[q2] = fmaf(xv, cps[q2][c], sacc[q2]);
            }
            float bdx = 3.4e38f; jf = 0x7fffffff;
            #pragma unroll
            for (int q2 = 0; q2 < CMAX; ++q2){
                if (q2 < ncand){
                    float d = fmaf(-2.f, sacc[q2], cbn_s[cj[q2]]);
                    if (d < bdx || (d == bdx && cj[q2] < jf)){ bdx = d; jf = cj[q2]; }
                }
            }
        }
        sidx[m] = jf;
        atomicAdd(&g_counts[jf], 1);
    }
    __syncthreads();

    // ---- fused output: gather q, straight-through write, commit partial ----
    float* qt = (float*)(sm + SB);              // 128 x 36 floats (B region retired)
    float csum = 0.f;
    for (int cc = 0; cc < 16; ++cc){            // chunks of 32 c
        __syncthreads();
        #pragma unroll
        for (int it = 0; it < 2; ++it){
            int i = tid + it*NTHR;              // 0..1023 float4s
            int t = i >> 3, c4 = i & 7;
            float4 v = *(const float4*)(cb + (size_t)sidx[t]*CD + cc*32 + c4*4);
            *(float4*)&qt[t*36 + c4*4] = v;
        }
        __syncthreads();
        {
            int t = tid & 127, h = tid >> 7;    // h in 0..3
            #pragma unroll
            for (int cl = 0; cl < 8; ++cl){
                int c = h*8 + cl;
                float q  = qt[t*36 + c];
                float xv = xblk[(size_t)(cc*32 + c)*TD + t];
                outblk[(size_t)(cc*32 + c)*TD + t] = __fadd_rn(xv, __fsub_rn(q, xv));
                float df = __fsub_rn(xv, q);
                csum = fmaf(df, df, csum);
            }
        }
    }
    #pragma unroll
    for (int o = 16; o; o >>= 1) csum += __shfl_xor_sync(~0u, csum, o);
    __syncthreads();
    if ((tid & 31) == 0) wred[tid >> 5] = csum;
    __syncthreads();
    if (tid == 0){
        float s = 0.f;
        #pragma unroll
        for (int w = 0; w < 16; ++w) s += wred[w];
        g_partials[b] = s;
    }
}

// ---------------- kernel 2: finalize commit loss + perplexity ----------------
__global__ void k_final(float* __restrict__ out){
    __shared__ double sd[256];
    int tid = threadIdx.x;
    double s = 0.0;
    for (int i = tid; i < NTILE; i += 256) s += (double)g_partials[i];
    sd[tid] = s; __syncthreads();
    for (int o = 128; o; o >>= 1){ if (tid < o) sd[tid] += sd[tid + o]; __syncthreads(); }
    double commit = sd[0] / ((double)NT * (double)CD);
    __syncthreads();
    double e = 0.0;
    for (int i = tid; i < NB; i += 256){
        double p = (double)g_counts[i] / (double)NT;
        e += p * log(p + 1e-7);
    }
    sd[tid] = e; __syncthreads();
    for (int o = 128; o; o >>= 1){ if (tid < o) sd[tid] += sd[tid + o]; __syncthreads(); }
    if (tid == 0){
        out[(size_t)NN*CD*TD]     = (float)commit;
        out[(size_t)NN*CD*TD + 1] = (float)exp(-sd[0]);
    }
}

extern "C" void kernel_launch(void* const* d_in, const int* in_sizes, int n_in,
                              void* d_out, int out_size){
    const float* x  = (const float*)d_in[0];   // (32, 512, 2048) fp32
    const float* cb = (const float*)d_in[1];   // (1024, 512) fp32
    float* out = (float*)d_out;

    cudaFuncSetAttribute(k_main, cudaFuncAttributeMaxDynamicSharedMemorySize, SMTOT);

    k_prep<<<NB, 128>>>(cb);
    k_main<<<NTILE, NTHR, SMTOT>>>(x, cb, out);
    k_final<<<1, 256>>>(out);
}

// round 8
// speedup vs baseline: 1.7010x; 1.7010x over previous
#include <cuda_runtime.h>
#include <cuda_fp16.h>
#include <cstdint>

#define NB   1024
#define CD   512
#define NN   32
#define TD   2048
#define NT   (NN*TD)      // 65536 rows
#define MT   128          // rows per CTA
#define NTILE (NT/MT)     // 512 CTAs
#define NTHR 512
#define PASSES 8
#define PN   128          // codes per pass
#define KC   128          // k per chunk
#define NCH  4            // chunks per pass
#define CHT  (PASSES*NCH) // 32 chunks total
#define MARGIN 1.5f
#define CMAX 8

typedef unsigned long long ull;

__device__ __align__(16) __half g_cb16[NB*CD];
__device__ float g_cbnorm[NB];
__device__ int   g_counts[NB];
__device__ float g_partials[NTILE];

// smem map (bytes): A 128x512 fp16 swizzled @0 (131072; later qt staging),
// B 2x32768 @131072 (later cand 64KB), cbn @196608 (4096), sidx @200704 (512), wred @201216
#define SA    0
#define SB    131072
#define SCBN  196608
#define SIDX  200704
#define SWRED 201216
#define SMTOT 201344

static __device__ __forceinline__ uint32_t smem_u32(const void* p){
    uint32_t a; asm("{ .reg .u64 t; cvta.to.shared.u64 t, %1; cvt.u32.u64 %0, t; }" : "=r"(a) : "l"(p));
    return a;
}
static __device__ __forceinline__ uint32_t A_off(int r, int c){
    int ck = c >> 3;
    int cks = (ck & ~7) | ((ck ^ r) & 7);
    return (uint32_t)(r*1024 + cks*16 + (c&7)*2);
}
static __device__ __forceinline__ uint32_t B_off(int j, int kk){
    int ck = kk >> 3;
    int cks = (ck & 8) | ((ck ^ j) & 7);
    return (uint32_t)(j*256 + cks*16 + (kk&7)*2);
}
static __device__ __forceinline__ void ldsm4(uint32_t* r, uint32_t addr){
    asm volatile("ldmatrix.sync.aligned.m8n8.x4.shared.b16 {%0,%1,%2,%3}, [%4];"
        : "=r"(r[0]), "=r"(r[1]), "=r"(r[2]), "=r"(r[3]) : "r"(addr));
}
// f16 accumulate: D/C are 2 x .f16x2 regs
static __device__ __forceinline__ void mma16816h(uint32_t* c, const uint32_t* a, uint32_t b0, uint32_t b1){
    asm volatile("mma.sync.aligned.m16n8k16.row.col.f16.f16.f16.f16 "
        "{%0,%1}, {%2,%3,%4,%5}, {%6,%7}, {%0,%1};"
        : "+r"(c[0]), "+r"(c[1])
        : "r"(a[0]), "r"(a[1]), "r"(a[2]), "r"(a[3]), "r"(b0), "r"(b1));
}

// ---------------- kernel 0: codebook norms + fp16 convert + zero counts ----------------
__global__ void k_norms(const float* __restrict__ cb){
    int j = blockIdx.x;
    float s = 0.f;
    for (int c = threadIdx.x; c < CD; c += 128){
        float v = cb[(size_t)j*CD + c];
        g_cb16[(size_t)j*CD + c] = __float2half_rn(v);
        s = fmaf(v, v, s);
    }
    #pragma unroll
    for (int o = 16; o; o >>= 1) s += __shfl_xor_sync(~0u, s, o);
    __shared__ float ws[4];
    if ((threadIdx.x & 31) == 0) ws[threadIdx.x >> 5] = s;
    __syncthreads();
    if (threadIdx.x == 0){
        g_cbnorm[j] = (ws[0] + ws[1]) + (ws[2] + ws[3]);
        g_counts[j] = 0;
    }
}

// ---------------- B chunk stage via cp.async (512 threads) ----------------
static __device__ __forceinline__ void issueB(int q, int tid, uint32_t sbase){
    int p = q >> 2, kc = q & 3;
    const __half* src0 = g_cb16 + (size_t)p*PN*CD + kc*KC;
    uint32_t bufb = sbase + SB + (uint32_t)(q & 1)*32768u;
    #pragma unroll
    for (int it = 0; it < 4; ++it){
        int idx = tid + it*NTHR;              // 0..2047 16B units
        int j = idx >> 4, ck = idx & 15;
        uint32_t dst = bufb + (uint32_t)(j*256 + (((ck & 8) | ((ck ^ j) & 7)) << 4));
        const void* srcp = (const void*)(src0 + (size_t)j*CD + ck*8);
        asm volatile("cp.async.cg.shared.global [%0], [%1], 16;" :: "r"(dst), "l"(srcp));
    }
    asm volatile("cp.async.commit_group;");
}

// ---------------- kernel 1: fused fp16 GEMM + top2 + refine + output + commit ----------------
__global__ __launch_bounds__(NTHR, 1)
void k_main(const float* __restrict__ x, const float* __restrict__ cb, float* __restrict__ out){
    extern __shared__ char sm[];
    const uint32_t sbase = smem_u32(sm);
    const int tid = threadIdx.x;
    const int wid = tid >> 5, l = tid & 31;
    const int wm = wid >> 3, wn = wid & 7;        // 2 M-warps x 8 N-warps
    const int b = blockIdx.x, n = b >> 4, t0 = (b & 15) * MT;
    const float* xblk = x + (size_t)n*CD*TD + t0;
    float* outblk     = out + (size_t)n*CD*TD + t0;
    float* cbn_s = (float*)(sm + SCBN);
    int*   sidx  = (int*)(sm + SIDX);
    float* wred  = (float*)(sm + SWRED);

    for (int i = tid; i < NB; i += NTHR) cbn_s[i] = g_cbnorm[i];

    // ---- stage A: x tile -> fp16, swizzled [t][c] ----
    #pragma unroll 4
    for (int it = 0; it < 64; ++it){
        int idx = tid + it*NTHR;
        int t = idx & 127, c = (idx >> 7) * 2;
        float v0 = xblk[(size_t)c*TD + t];
        float v1 = xblk[(size_t)(c+1)*TD + t];
        __half2 pk = __floats2half2_rn(v0, v1);
        *(__half2*)(sm + SA + A_off(t, c)) = pk;
    }
    __syncthreads();

    issueB(0, tid, sbase);

    float bd[8][2]; int bj[8][2];
    #pragma unroll
    for (int r = 0; r < 8; ++r){
        bd[r][0] = bd[r][1] = 3.4e38f; bj[r][0] = bj[r][1] = 0;
    }

    const int arow = wm*64 + ((l >> 3) & 1)*8 + (l & 7);
    const int brow = wn*16 + (l >> 4)*8 + (l & 7);

    for (int p = 0; p < PASSES; ++p){
        uint32_t acc[4][2][2];                 // [ti][tj][reg] .f16x2
        #pragma unroll
        for (int ti = 0; ti < 4; ++ti)
            #pragma unroll
            for (int tj = 0; tj < 2; ++tj){ acc[ti][tj][0] = 0u; acc[ti][tj][1] = 0u; }

        for (int kc = 0; kc < NCH; ++kc){
            int q = p*NCH + kc;
            if (q + 1 < CHT){ issueB(q + 1, tid, sbase); asm volatile("cp.async.wait_group 1;"); }
            else            { asm volatile("cp.async.wait_group 0;"); }
            __syncthreads();
            uint32_t bufb = sbase + SB + (uint32_t)(q & 1)*32768u;

            #pragma unroll
            for (int ks = 0; ks < 8; ++ks){
                const int acol = kc*KC + ks*16 + (l >> 4)*8;
                const int bcol = ks*16 + ((l >> 3) & 1)*8;
                uint32_t a[4][4], bf[4];
                #pragma unroll
                for (int ti = 0; ti < 4; ++ti)
                    ldsm4(a[ti], sbase + SA + A_off(arow + ti*16, acol));
                ldsm4(bf, bufb + B_off(brow, bcol));
                #pragma unroll
                for (int ti = 0; ti < 4; ++ti)
                    #pragma unroll
                    for (int tj = 0; tj < 2; ++tj)
                        mma16816h(acc[ti][tj], a[ti], bf[tj*2], bf[tj*2+1]);
            }
            __syncthreads();
        }
        // ---- pass epilogue: distances -> per-(row-slot) top2 ----
        #pragma unroll
        for (int ti = 0; ti < 4; ++ti)
            #pragma unroll
            for (int tj = 0; tj < 2; ++tj)
                #pragma unroll
                for (int dreg = 0; dreg < 2; ++dreg){
                    float2 f = __half22float2(*(__half2*)&acc[ti][tj][dreg]);
                    int jg0 = p*PN + wn*16 + tj*8 + (l & 3)*2;
                    float d0 = fmaf(-2.f, f.x, cbn_s[jg0]);
                    float d1 = fmaf(-2.f, f.y, cbn_s[jg0 + 1]);
                    int r = ti*2 + dreg;
                    if (d0 < bd[r][0]){
                        bd[r][1] = bd[r][0]; bj[r][1] = bj[r][0];
                        bd[r][0] = d0;       bj[r][0] = jg0;
                    } else if (d0 < bd[r][1]){
                        bd[r][1] = d0;       bj[r][1] = jg0;
                    }
                    if (d1 < bd[r][0]){
                        bd[r][1] = bd[r][0]; bj[r][1] = bj[r][0];
                        bd[r][0] = d1;       bj[r][0] = jg0 + 1;
                    } else if (d1 < bd[r][1]){
                        bd[r][1] = d1;       bj[r][1] = jg0 + 1;
                    }
                }
    }

    // ---- dump candidates (overlay B buffers): cand[128][64] of (d, j) ----
    float2* cand = (float2*)(sm + SB);
    #pragma unroll
    for (int r = 0; r < 8; ++r){
        int m = wm*64 + (r >> 1)*16 + (r & 1)*8 + (l >> 2);
        int slot = wn*8 + (l & 3)*2;
        cand[m*64 + slot + 0] = make_float2(bd[r][0], __int_as_float(bj[r][0]));
        cand[m*64 + slot + 1] = make_float2(bd[r][1], __int_as_float(bj[r][1]));
    }
    __syncthreads();

    // ---- per-row pick + exact fp32 refine if margin small ----
    if (tid < MT){
        int m = tid;
        float b1 = 3.4e38f; int j1 = 0x7fffffff;
        #pragma unroll 4
        for (int s = 0; s < 64; ++s){
            float2 e = cand[m*64 + s];
            int j = __float_as_int(e.y);
            if (e.x < b1 || (e.x == b1 && j < j1)){ b1 = e.x; j1 = j; }
        }
        int cj[CMAX]; int ncand = 0;
        #pragma unroll 4
        for (int s = 0; s < 64; ++s){
            float2 e = cand[m*64 + s];
            if (e.x <= b1 + MARGIN && ncand < CMAX) cj[ncand++] = __float_as_int(e.y);
        }
        int jf = j1;
        if (ncand > 1){
            float sacc[CMAX];
            const float* cps[CMAX];
            #pragma unroll
            for (int q2 = 0; q2 < CMAX; ++q2){
                sacc[q2] = 0.f;
                cps[q2] = cb + (size_t)cj[q2 < ncand ? q2 : 0]*CD;
            }
            const float* xr = xblk + m;
            #pragma unroll 4
            for (int c = 0; c < CD; ++c){
                float xv = xr[(size_t)c*TD];
                #pragma unroll
                for (int q2 = 0; q2 < CMAX; ++q2)
                    if (q2 < ncand) sacc[q2] = fmaf(xv, cps[q2][c], sacc[q2]);
            }
            float bdx = 3.4e38f; jf = 0x7fffffff;
            #pragma unroll
            for (int q2 = 0; q2 < CMAX; ++q2){
                if (q2 < ncand){
                    float d = fmaf(-2.f, sacc[q2], cbn_s[cj[q2]]);
                    if (d < bdx || (d == bdx && cj[q2] < jf)){ bdx = d; jf = cj[q2]; }
                }
            }
        }
        sidx[m] = jf;
        atomicAdd(&g_counts[jf], 1);
    }
    __syncthreads();

    // ---- fused output: gather q, straight-through write, commit partial ----
    float* qt = (float*)(sm + SA);              // 128 x 36 floats (A region retired)
    float csum = 0.f;
    for (int cc = 0; cc < 16; ++cc){            // chunks of 32 c
        __syncthreads();
        #pragma unroll
        for (int it = 0; it < 2; ++it){
            int i = tid + it*NTHR;              // 0..1023 float4s
            int t = i >> 3, c4 = i & 7;
            float4 v = *(const float4*)(cb + (size_t)sidx[t]*CD + cc*32 + c4*4);
            *(float4*)&qt[t*36 + c4*4] = v;
        }
        __syncthreads();
        {
            int t = tid & 127, h = tid >> 7;    // h in 0..3
            #pragma unroll
            for (int cl = 0; cl < 8; ++cl){
                int c = h*8 + cl;
                float q  = qt[t*36 + c];
                float xv = xblk[(size_t)(cc*32 + c)*TD + t];
                outblk[(size_t)(cc*32 + c)*TD + t] = __fadd_rn(xv, __fsub_rn(q, xv));
                float df = __fsub_rn(xv, q);
                csum = fmaf(df, df, csum);
            }
        }
    }
    #pragma unroll
    for (int o = 16; o; o >>= 1) csum += __shfl_xor_sync(~0u, csum, o);
    __syncthreads();
    if ((tid & 31) == 0) wred[tid >> 5] = csum;
    __syncthreads();
    if (tid == 0){
        float s = 0.f;
        #pragma unroll
        for (int w = 0; w < 16; ++w) s += wred[w];
        g_partials[b] = s;
    }
}

// ---------------- kernel 2: finalize commit loss + perplexity ----------------
__global__ void k_final(float* __restrict__ out){
    __shared__ double sd[256];
    int tid = threadIdx.x;
    double s = 0.0;
    for (int i = tid; i < NTILE; i += 256) s += (double)g_partials[i];
    sd[tid] = s; __syncthreads();
    for (int o = 128; o; o >>= 1){ if (tid < o) sd[tid] += sd[tid + o]; __syncthreads(); }
    double commit = sd[0] / ((double)NT * (double)CD);
    __syncthreads();
    double e = 0.0;
    for (int i = tid; i < NB; i += 256){
        double p = (double)g_counts[i] / (double)NT;
        e += p * log(p + 1e-7);
    }
    sd[tid] = e; __syncthreads();
    for (int o = 128; o; o >>= 1){ if (tid < o) sd[tid] += sd[tid + o]; __syncthreads(); }
    if (tid == 0){
        out[(size_t)NN*CD*TD]     = (float)commit;
        out[(size_t)NN*CD*TD + 1] = (float)exp(-sd[0]);
    }
}

extern "C" void kernel_launch(void* const* d_in, const int* in_sizes, int n_in,
                              void* d_out, int out_size){
    const float* x  = (const float*)d_in[0];   // (32, 512, 2048) fp32
    const float* cb = (const float*)d_in[1];   // (1024, 512) fp32
    float* out = (float*)d_out;

    cudaFuncSetAttribute(k_main, cudaFuncAttributeMaxDynamicSharedMemorySize, SMTOT);

    k_norms<<<NB, 128>>>(cb);
    k_main<<<NTILE, NTHR, SMTOT>>>(x, cb, out);
    k_final<<<1, 256>>>(out);
}